// round 15
// baseline (speedup 1.0000x reference)
#include <cuda_runtime.h>
#include <cuda_bf16.h>
#include <cuda_fp16.h>
#include <cstdint>

#define B_ 32
// smem (bytes): K ring 3x16384 at 0 | V ring 3x16384 at 49152 | mask 16384 at 98304
#define OFF_KR    0
#define OFF_VR    49152
#define OFF_MASK  98304
#define SMEM_TOTAL 114688

// preconverted K/V scratch: bf16 hi/lo, row-major 128B rows
__device__ __align__(16) unsigned char g_kh[(size_t)B_*1024*128];
__device__ __align__(16) unsigned char g_kl[(size_t)B_*1024*128];
__device__ __align__(16) unsigned char g_vh[(size_t)B_*1024*128];
__device__ __align__(16) unsigned char g_vl[(size_t)B_*1024*128];

__device__ __forceinline__ uint32_t s2u(const void* p){
    uint32_t a; asm("{ .reg .u64 t; cvta.to.shared.u64 t, %1; cvt.u32.u64 %0, t; }":"=r"(a):"l"(p)); return a;
}
__device__ __forceinline__ void ldsm4(uint32_t* r, uint32_t a){
    asm volatile("ldmatrix.sync.aligned.m8n8.x4.shared.b16 {%0,%1,%2,%3}, [%4];"
        :"=r"(r[0]),"=r"(r[1]),"=r"(r[2]),"=r"(r[3]):"r"(a));
}
__device__ __forceinline__ void ldsm4t(uint32_t* r, uint32_t a){
    asm volatile("ldmatrix.sync.aligned.m8n8.x4.trans.shared.b16 {%0,%1,%2,%3}, [%4];"
        :"=r"(r[0]),"=r"(r[1]),"=r"(r[2]),"=r"(r[3]):"r"(a));
}
__device__ __forceinline__ void mma_bf16(float* c, const uint32_t* a, const uint32_t* b){
    asm volatile("mma.sync.aligned.m16n8k16.row.col.f32.bf16.bf16.f32 "
        "{%0,%1,%2,%3}, {%4,%5,%6,%7}, {%8,%9}, {%0,%1,%2,%3};"
        :"+f"(c[0]),"+f"(c[1]),"+f"(c[2]),"+f"(c[3])
        :"r"(a[0]),"r"(a[1]),"r"(a[2]),"r"(a[3]),"r"(b[0]),"r"(b[1]));
}
__device__ __forceinline__ uint32_t swa(uint32_t base, int row, int u){
    return base + (uint32_t)row*128u + (uint32_t)((u ^ (row & 7)) << 4);
}
__device__ __forceinline__ void split2(float x, float y, uint32_t &hi, uint32_t &lo){
    __nv_bfloat16 hx=__float2bfloat16(x), hy=__float2bfloat16(y);
    __nv_bfloat16 lx=__float2bfloat16(x-__bfloat162float(hx)), ly=__float2bfloat16(y-__bfloat162float(hy));
    hi = ((uint32_t)__bfloat16_as_ushort(hy)<<16)|__bfloat16_as_ushort(hx);
    lo = ((uint32_t)__bfloat16_as_ushort(ly)<<16)|__bfloat16_as_ushort(lx);
}
__device__ __forceinline__ void cvt_store(float4 v, char* smc, int offH, int offL, int row, int c4){
    uint32_t o = (uint32_t)row*128u + (uint32_t)(((((c4>>1) ^ (row&7)) << 4)) | ((c4&1)<<3));
    uint32_t h0, l0, h1, l1;
    split2(v.x, v.y, h0, l0);
    split2(v.z, v.w, h1, l1);
    *(uint2*)(smc + offH + o) = make_uint2(h0, h1);
    *(uint2*)(smc + offL + o) = make_uint2(l0, l1);
}
__device__ __forceinline__ void cpa16(uint32_t dst, const void* src){
    asm volatile("cp.async.cg.shared.global [%0], [%1], 16;" :: "r"(dst), "l"(src));
}
#define CPA_COMMIT() asm volatile("cp.async.commit_group;" ::: "memory")
#define CPA_WAIT1()  asm volatile("cp.async.wait_group 1;" ::: "memory")
#define CPA_WAIT0()  asm volatile("cp.async.wait_group 0;" ::: "memory")

// load one 64-row tile (hi 8KB + lo 8KB) into a 16KB slot; 1024 16B chunks, 4/thread
__device__ __forceinline__ void load_tile(uint32_t slotbase, const unsigned char* ghi,
                                          const unsigned char* glo, size_t row0, int tid){
    #pragma unroll
    for (int p = 0; p < 4; p++){
        int id = tid + p*256;
        int hl = id >> 9, rem = id & 511, r = rem >> 3, u = rem & 7;
        uint32_t dst = slotbase + (uint32_t)hl*8192u + (uint32_t)r*128u + (uint32_t)((u ^ (r & 7)) << 4);
        const unsigned char* src = (hl ? glo : ghi) + (row0 + r)*128 + u*16;
        cpa16(dst, src);
    }
}

__global__ void __launch_bounds__(512) preconv(const float* __restrict__ K, const float* __restrict__ V){
    size_t idx = (size_t)blockIdx.x * 512 + threadIdx.x;
    size_t row = idx >> 4, c4 = idx & 15;
    float4 kv = ((const float4*)K)[idx];
    float4 vv = ((const float4*)V)[idx];
    uint32_t h0,l0,h1,l1;
    split2(kv.x, kv.y, h0, l0); split2(kv.z, kv.w, h1, l1);
    *(uint2*)(g_kh + row*128 + c4*8) = make_uint2(h0, h1);
    *(uint2*)(g_kl + row*128 + c4*8) = make_uint2(l0, l1);
    split2(vv.x, vv.y, h0, l0); split2(vv.z, vv.w, h1, l1);
    *(uint2*)(g_vh + row*128 + c4*8) = make_uint2(h0, h1);
    *(uint2*)(g_vl + row*128 + c4*8) = make_uint2(l0, l1);
}

__global__ void __launch_bounds__(256, 2)
mha_hmma(const float* __restrict__ Qg, const int* __restrict__ Mg,
         const float* __restrict__ QMg, float* __restrict__ outR, float* __restrict__ outA)
{
    extern __shared__ char smc[];
    const uint32_t sb = s2u(smc);
    const int tid = threadIdx.x, wid = tid>>5, ln = tid&31;
    const int la = ln&3;
    const int r0 = 16*wid + (ln>>2), r1 = r0 + 8;
    const int b = blockIdx.x>>3, q0 = (blockIdx.x&7)*128;
    const size_t brow = (size_t)b*1024;

    // ---- prologue: Q (x0.125) -> bf16 split into K-ring slots 0/1; mask bitmask ----
    const float4* gQ4 = (const float4*)(Qg + (brow + q0)*64);
    for (int i = tid; i < 2048; i += 256){
        float4 v = gQ4[i];
        v.x*=0.125f; v.y*=0.125f; v.z*=0.125f; v.w*=0.125f;
        cvt_store(v, smc, OFF_KR, OFF_KR + 16384, i>>4, i&15);
    }
    uint32_t* mbm = (uint32_t*)(smc + OFF_MASK);
    const int* gM = Mg + (brow + q0)*1024;
    for (int i = tid; i < 4096; i += 256){
        const int4* mp = (const int4*)(gM + ((size_t)(i>>5))*1024 + (i&31)*32);
        uint32_t bits = 0;
        #pragma unroll
        for (int m2 = 0; m2 < 8; m2++){
            int4 v = mp[m2];
            bits |= ((v.x?1u:0u)|(v.y?2u:0u)|(v.z?4u:0u)|(v.w?8u:0u)) << (4*m2);
        }
        mbm[i] = bits;
    }
    __syncthreads();
    // Q fragments register-resident
    const int qrow = 16*wid + (ln&15);
    uint32_t Qh[4][4], Ql[4][4];
    #pragma unroll
    for (int c = 0; c < 4; c++){
        ldsm4(Qh[c], swa(sb + OFF_KR,         qrow, 2*c + (ln>>4)));
        ldsm4(Ql[c], swa(sb + OFF_KR + 16384, qrow, 2*c + (ln>>4)));
    }
    __syncthreads();   // ring free for K/V

    // ---- 3-stage pipeline prologue: issue tiles 0 and 1 ----
    load_tile(sb + OFF_KR,         g_kh, g_kl, brow,      tid);
    load_tile(sb + OFF_VR,         g_vh, g_vl, brow,      tid); CPA_COMMIT();
    load_tile(sb + OFF_KR + 16384, g_kh, g_kl, brow + 64, tid);
    load_tile(sb + OFF_VR + 16384, g_vh, g_vl, brow + 64, tid); CPA_COMMIT();

    float rs0 = 0.f, rs1 = 0.f;
    float o[8][4];
    #pragma unroll
    for (int j=0;j<8;j++){ o[j][0]=0.f; o[j][1]=0.f; o[j][2]=0.f; o[j][3]=0.f; }

    for (int t = 0; t < 16; t++){
        if (t < 15) CPA_WAIT1(); else CPA_WAIT0();
        __syncthreads();   // tile t visible; slot (t+2)%3 readers (iter t-1) finished
        if (t + 2 < 16){
            uint32_t slot = ((t+2)%3)*16384u;
            load_tile(sb + OFF_KR + slot, g_kh, g_kl, brow + 64*(t+2), tid);
            load_tile(sb + OFF_VR + slot, g_vh, g_vl, brow + 64*(t+2), tid);
            CPA_COMMIT();
        }
        const uint32_t cslot = (uint32_t)(t%3)*16384u;
        const uint32_t bh_base = sb + OFF_KR + cslot, bl_base = bh_base + 8192;
        const uint32_t vh_base = sb + OFF_VR + cslot, vl_base = vh_base + 8192;
        float s[8][4];
        #pragma unroll
        for (int j=0;j<8;j++){ s[j][0]=0.f; s[j][1]=0.f; s[j][2]=0.f; s[j][3]=0.f; }
        #pragma unroll
        for (int c = 0; c < 4; c++){
            #pragma unroll
            for (int jp = 0; jp < 4; jp++){
                uint32_t bh[4], bl[4];
                int krow = 16*jp + ((ln>>4)<<3) + (ln&7);
                int ku = 2*c + ((ln>>3)&1);
                ldsm4(bh, swa(bh_base, krow, ku));
                ldsm4(bl, swa(bl_base, krow, ku));
                mma_bf16(s[2*jp],   Qh[c], bh);   mma_bf16(s[2*jp],   Qh[c], bl);   mma_bf16(s[2*jp],   Ql[c], bh);
                mma_bf16(s[2*jp+1], Qh[c], bh+2); mma_bf16(s[2*jp+1], Qh[c], bl+2); mma_bf16(s[2*jp+1], Ql[c], bh+2);
            }
        }
        // masked exp (unnormalized) + rowsum accumulation
        {
            uint32_t w0a = mbm[r0*32 + 2*t], w0b = mbm[r0*32 + 2*t + 1];
            uint32_t w1a = mbm[r1*32 + 2*t], w1b = mbm[r1*32 + 2*t + 1];
            #pragma unroll
            for (int j = 0; j < 8; j++){
                uint32_t wr0 = (j<4)?w0a:w0b, wr1 = (j<4)?w1a:w1b;
                int bit = 8*(j&3) + 2*la;
                float e0 = ((wr0>>bit)&1u)     ? 0.f : __expf(s[j][0]);
                float e1 = ((wr0>>(bit+1))&1u) ? 0.f : __expf(s[j][1]);
                float e2 = ((wr1>>bit)&1u)     ? 0.f : __expf(s[j][2]);
                float e3 = ((wr1>>(bit+1))&1u) ? 0.f : __expf(s[j][3]);
                rs0 += e0 + e1;  rs1 += e2 + e3;
                s[j][0] = e0; s[j][1] = e1; s[j][2] = e2; s[j][3] = e3;
            }
        }
        // store unnormalized e as fp16 packed into the FIRST 2KB of each attn row
        {
            uint16_t* e0p = (uint16_t*)(outA + (brow + q0 + r0)*1024) + t*64 + 2*la;
            uint16_t* e1p = (uint16_t*)(outA + (brow + q0 + r1)*1024) + t*64 + 2*la;
            #pragma unroll
            for (int j=0;j<8;j++){
                *(__half2*)(e0p + 8*j) = __floats2half2_rn(s[j][0], s[j][1]);
                *(__half2*)(e1p + 8*j) = __floats2half2_rn(s[j][2], s[j][3]);
            }
        }
        // PV with unnormalized e (O scaled once at the end)
        #pragma unroll
        for (int c2 = 0; c2 < 4; c2++){
            uint32_t ah[4], al[4];
            split2(s[2*c2][0],   s[2*c2][1],   ah[0], al[0]);
            split2(s[2*c2][2],   s[2*c2][3],   ah[1], al[1]);
            split2(s[2*c2+1][0], s[2*c2+1][1], ah[2], al[2]);
            split2(s[2*c2+1][2], s[2*c2+1][3], ah[3], al[3]);
            #pragma unroll
            for (int jp=0;jp<4;jp++){
                uint32_t bh[4], bl[4];
                int vrow = 16*c2 + ((ln>>3)&1)*8 + (ln&7);
                int vu = 2*jp + (ln>>4);
                ldsm4t(bh, swa(vh_base, vrow, vu));
                ldsm4t(bl, swa(vl_base, vrow, vu));
                mma_bf16(o[2*jp],   ah, bh);   mma_bf16(o[2*jp],   ah, bl);   mma_bf16(o[2*jp],   al, bh);
                mma_bf16(o[2*jp+1], ah, bh+2); mma_bf16(o[2*jp+1], ah, bl+2); mma_bf16(o[2*jp+1], al, bh+2);
            }
        }
    }

    // ---- rowsums -> scale factors ----
    rs0 += __shfl_xor_sync(~0u, rs0, 1); rs0 += __shfl_xor_sync(~0u, rs0, 2);
    rs1 += __shfl_xor_sync(~0u, rs1, 1); rs1 += __shfl_xor_sync(~0u, rs1, 2);
    const float qm0 = QMg[brow + q0 + r0], qm1 = QMg[brow + q0 + r1];
    const float scl0 = (rs0>0.f) ? (qm0/rs0) : 0.f, uad0 = (rs0>0.f) ? 0.f : qm0*(1.f/1024.f);
    const float scl1 = (rs1>0.f) ? (qm1/rs1) : 0.f, uad1 = (rs1>0.f) ? 0.f : qm1*(1.f/1024.f);

    // ---- O: scale in registers, store ----
    {
        float* oR = outR + (brow + q0)*64;
        #pragma unroll
        for (int j=0;j<8;j++){
            *(float2*)(oR + (size_t)r0*64 + 8*j + 2*la) = make_float2(o[j][0]*scl0, o[j][1]*scl0);
            *(float2*)(oR + (size_t)r1*64 + 8*j + 2*la) = make_float2(o[j][2]*scl1, o[j][3]*scl1);
        }
    }

    // ---- attn tail: expand this warp's 16 rows fp16 -> fp32 in place ----
    __syncwarp();
    __threadfence_block();   // order e-stores before cross-lane re-reads (same SM/L1)
    #pragma unroll 1
    for (int rr = 0; rr < 16; rr++){
        float scl_v = (rr < 8) ? __shfl_sync(~0u, scl0, rr*4) : __shfl_sync(~0u, scl1, (rr-8)*4);
        float uad_v = (rr < 8) ? __shfl_sync(~0u, uad0, rr*4) : __shfl_sync(~0u, uad1, (rr-8)*4);
        float* rowp = outA + (brow + q0 + 16*wid + rr)*1024;
        uint4 ebuf[4];
        #pragma unroll
        for (int i = 0; i < 4; i++) ebuf[i] = ((const uint4*)rowp)[ln + 32*i];
        __syncwarp();
        #pragma unroll
        for (int i = 0; i < 4; i++){
            __half2* hp = (__half2*)&ebuf[i];
            float2 a = __half22float2(hp[0]), bq = __half22float2(hp[1]);
            float2 c = __half22float2(hp[2]), d = __half22float2(hp[3]);
            float4 o0 = make_float4(a.x*scl_v+uad_v, a.y*scl_v+uad_v, bq.x*scl_v+uad_v, bq.y*scl_v+uad_v);
            float4 o1 = make_float4(c.x*scl_v+uad_v, c.y*scl_v+uad_v, d.x*scl_v+uad_v, d.y*scl_v+uad_v);
            ((float4*)rowp)[2*(ln + 32*i)]     = o0;
            ((float4*)rowp)[2*(ln + 32*i) + 1] = o1;
        }
        __syncwarp();
    }
}

extern "C" void kernel_launch(void* const* d_in, const int* in_sizes, int n_in,
                              void* d_out, int out_size)
{
    const float* Kg  = (const float*)d_in[0];
    const float* Vg  = (const float*)d_in[1];
    const float* Qg  = (const float*)d_in[2];
    const int*   Mg  = (const int*)d_in[3];
    const float* QMg = (const float*)d_in[4];
    float* outR = (float*)d_out;
    float* outA = outR + (size_t)B_ * 1024 * 64;

    preconv<<<1024, 512>>>(Kg, Vg);
    cudaFuncSetAttribute(mha_hmma, cudaFuncAttributeMaxDynamicSharedMemorySize, SMEM_TOTAL);
    mha_hmma<<<B_ * 8, 256, SMEM_TOTAL>>>(Qg, Mg, QMg, outR, outA);
}

// round 16
// speedup vs baseline: 1.0319x; 1.0319x over previous
#include <cuda_runtime.h>
#include <cuda_bf16.h>
#include <cstdint>

#define B_ 32
// smem (bytes): K ring 2x16384 at 0 | V ring 2x16384 at 32768 | mask 32KB at 65536
#define OFF_RING  0
#define OFF_VRING 32768
#define OFF_MASK  65536
#define SMEM_TOTAL 98304

// preconverted K/V scratch: bf16 hi/lo, row-major 128B rows
__device__ __align__(16) unsigned char g_kh[(size_t)B_*1024*128];
__device__ __align__(16) unsigned char g_kl[(size_t)B_*1024*128];
__device__ __align__(16) unsigned char g_vh[(size_t)B_*1024*128];
__device__ __align__(16) unsigned char g_vl[(size_t)B_*1024*128];

__device__ __forceinline__ uint32_t s2u(const void* p){
    uint32_t a; asm("{ .reg .u64 t; cvta.to.shared.u64 t, %1; cvt.u32.u64 %0, t; }":"=r"(a):"l"(p)); return a;
}
__device__ __forceinline__ void ldsm4(uint32_t* r, uint32_t a){
    asm volatile("ldmatrix.sync.aligned.m8n8.x4.shared.b16 {%0,%1,%2,%3}, [%4];"
        :"=r"(r[0]),"=r"(r[1]),"=r"(r[2]),"=r"(r[3]):"r"(a));
}
__device__ __forceinline__ void ldsm4t(uint32_t* r, uint32_t a){
    asm volatile("ldmatrix.sync.aligned.m8n8.x4.trans.shared.b16 {%0,%1,%2,%3}, [%4];"
        :"=r"(r[0]),"=r"(r[1]),"=r"(r[2]),"=r"(r[3]):"r"(a));
}
__device__ __forceinline__ void mma_bf16(float* c, const uint32_t* a, const uint32_t* b){
    asm volatile("mma.sync.aligned.m16n8k16.row.col.f32.bf16.bf16.f32 "
        "{%0,%1,%2,%3}, {%4,%5,%6,%7}, {%8,%9}, {%0,%1,%2,%3};"
        :"+f"(c[0]),"+f"(c[1]),"+f"(c[2]),"+f"(c[3])
        :"r"(a[0]),"r"(a[1]),"r"(a[2]),"r"(a[3]),"r"(b[0]),"r"(b[1]));
}
__device__ __forceinline__ uint32_t swa(uint32_t base, int row, int u){
    return base + (uint32_t)row*128u + (uint32_t)((u ^ (row & 7)) << 4);
}
__device__ __forceinline__ void split2(float x, float y, uint32_t &hi, uint32_t &lo){
    __nv_bfloat16 hx=__float2bfloat16(x), hy=__float2bfloat16(y);
    __nv_bfloat16 lx=__float2bfloat16(x-__bfloat162float(hx)), ly=__float2bfloat16(y-__bfloat162float(hy));
    hi = ((uint32_t)__bfloat16_as_ushort(hy)<<16)|__bfloat16_as_ushort(hx);
    lo = ((uint32_t)__bfloat16_as_ushort(ly)<<16)|__bfloat16_as_ushort(lx);
}
__device__ __forceinline__ void cvt_store(float4 v, char* smc, int offH, int offL, int row, int c4){
    uint32_t o = (uint32_t)row*128u + (uint32_t)(((((c4>>1) ^ (row&7)) << 4)) | ((c4&1)<<3));
    uint32_t h0, l0, h1, l1;
    split2(v.x, v.y, h0, l0);
    split2(v.z, v.w, h1, l1);
    *(uint2*)(smc + offH + o) = make_uint2(h0, h1);
    *(uint2*)(smc + offL + o) = make_uint2(l0, l1);
}
__device__ __forceinline__ void cpa16(uint32_t dst, const void* src){
    asm volatile("cp.async.cg.shared.global [%0], [%1], 16;" :: "r"(dst), "l"(src));
}
#define CPA_COMMIT() asm volatile("cp.async.commit_group;" ::: "memory")
#define CPA_WAIT1()  asm volatile("cp.async.wait_group 1;" ::: "memory")
#define CPA_WAIT0()  asm volatile("cp.async.wait_group 0;" ::: "memory")

// load one 64-row tile (hi 8KB + lo 8KB) into a 16KB slot; 1024 16B chunks, 2/thread @512thr
__device__ __forceinline__ void load_tile(uint32_t slotbase, const unsigned char* ghi,
                                          const unsigned char* glo, size_t row0, int tid){
    #pragma unroll
    for (int p = 0; p < 2; p++){
        int id = tid + p*512;
        int hl = id >> 9, rem = id & 511, r = rem >> 3, u = rem & 7;
        uint32_t dst = slotbase + (uint32_t)hl*8192u + (uint32_t)r*128u + (uint32_t)((u ^ (r & 7)) << 4);
        const unsigned char* src = (hl ? glo : ghi) + (row0 + r)*128 + u*16;
        cpa16(dst, src);
    }
}

__global__ void __launch_bounds__(512) preconv(const float* __restrict__ K, const float* __restrict__ V){
    size_t idx = (size_t)blockIdx.x * 512 + threadIdx.x;
    size_t row = idx >> 4, c4 = idx & 15;
    float4 kv = ((const float4*)K)[idx];
    float4 vv = ((const float4*)V)[idx];
    uint32_t h0,l0,h1,l1;
    split2(kv.x, kv.y, h0, l0); split2(kv.z, kv.w, h1, l1);
    *(uint2*)(g_kh + row*128 + c4*8) = make_uint2(h0, h1);
    *(uint2*)(g_kl + row*128 + c4*8) = make_uint2(l0, l1);
    split2(vv.x, vv.y, h0, l0); split2(vv.z, vv.w, h1, l1);
    *(uint2*)(g_vh + row*128 + c4*8) = make_uint2(h0, h1);
    *(uint2*)(g_vl + row*128 + c4*8) = make_uint2(l0, l1);
}

__global__ void __launch_bounds__(512, 1)
mha_hmma(const float* __restrict__ Qg, const int* __restrict__ Mg,
         const float* __restrict__ QMg, float* __restrict__ outR, float* __restrict__ outA)
{
    extern __shared__ char smc[];
    const uint32_t sb = s2u(smc);
    const int tid = threadIdx.x, wid = tid>>5, ln = tid&31;
    const int la = ln&3;
    const int r0 = 16*wid + (ln>>2), r1 = r0 + 8;   // rows within 256-row q-block
    const int b = blockIdx.x>>2, q0 = (blockIdx.x&3)*256;
    const size_t brow = (size_t)b*1024;

    // ---- prologue: Q (x0.125) -> bf16 split (hi in K-ring 32KB, lo in V-ring 32KB); mask bitmask ----
    const float4* gQ4 = (const float4*)(Qg + (brow + q0)*64);
    for (int i = tid; i < 4096; i += 512){
        float4 v = gQ4[i];
        v.x*=0.125f; v.y*=0.125f; v.z*=0.125f; v.w*=0.125f;
        cvt_store(v, smc, OFF_RING, OFF_VRING, i>>4, i&15);
    }
    uint32_t* mbm = (uint32_t*)(smc + OFF_MASK);
    const int* gM = Mg + (brow + q0)*1024;
    for (int i = tid; i < 8192; i += 512){
        const int4* mp = (const int4*)(gM + ((size_t)(i>>5))*1024 + (i&31)*32);
        uint32_t bits = 0;
        #pragma unroll
        for (int m2 = 0; m2 < 8; m2++){
            int4 v = mp[m2];
            bits |= ((v.x?1u:0u)|(v.y?2u:0u)|(v.z?4u:0u)|(v.w?8u:0u)) << (4*m2);
        }
        mbm[i] = bits;
    }
    __syncthreads();
    // Q fragments register-resident
    const int qrow = 16*wid + (ln&15);
    uint32_t Qh[4][4], Ql[4][4];
    #pragma unroll
    for (int c = 0; c < 4; c++){
        ldsm4(Qh[c], swa(sb + OFF_RING,  qrow, 2*c + (ln>>4)));
        ldsm4(Ql[c], swa(sb + OFF_VRING, qrow, 2*c + (ln>>4)));
    }
    __syncthreads();   // rings free for K/V

    // ================= single pass: QK -> e (unnormalized) -> attn store + PV =================
    float rs0 = 0.f, rs1 = 0.f;
    float o[8][4];
    #pragma unroll
    for (int j=0;j<8;j++){ o[j][0]=0.f; o[j][1]=0.f; o[j][2]=0.f; o[j][3]=0.f; }

    load_tile(sb + OFF_RING,  g_kh, g_kl, brow, tid);
    load_tile(sb + OFF_VRING, g_vh, g_vl, brow, tid); CPA_COMMIT();
    for (int t = 0; t < 16; t++){
        if (t < 15){
            load_tile(sb + OFF_RING  + ((t+1)&1)*16384, g_kh, g_kl, brow + 64*(t+1), tid);
            load_tile(sb + OFF_VRING + ((t+1)&1)*16384, g_vh, g_vl, brow + 64*(t+1), tid);
            CPA_COMMIT();
        }
        if (t < 15) CPA_WAIT1(); else CPA_WAIT0();
        __syncthreads();
        const uint32_t bh_base = sb + OFF_RING  + (t&1)*16384, bl_base = bh_base + 8192;
        const uint32_t vh_base = sb + OFF_VRING + (t&1)*16384, vl_base = vh_base + 8192;
        float s[8][4];
        #pragma unroll
        for (int j=0;j<8;j++){ s[j][0]=0.f; s[j][1]=0.f; s[j][2]=0.f; s[j][3]=0.f; }
        #pragma unroll
        for (int c = 0; c < 4; c++){
            #pragma unroll
            for (int jp = 0; jp < 4; jp++){
                uint32_t bh[4], bl[4];
                int krow = 16*jp + ((ln>>4)<<3) + (ln&7);
                int ku = 2*c + ((ln>>3)&1);
                ldsm4(bh, swa(bh_base, krow, ku));
                ldsm4(bl, swa(bl_base, krow, ku));
                mma_bf16(s[2*jp],   Qh[c], bh);   mma_bf16(s[2*jp],   Qh[c], bl);   mma_bf16(s[2*jp],   Ql[c], bh);
                mma_bf16(s[2*jp+1], Qh[c], bh+2); mma_bf16(s[2*jp+1], Qh[c], bl+2); mma_bf16(s[2*jp+1], Ql[c], bh+2);
            }
        }
        // masked exp (unnormalized) + rowsum accumulation
        {
            uint32_t w0a = mbm[r0*32 + 2*t], w0b = mbm[r0*32 + 2*t + 1];
            uint32_t w1a = mbm[r1*32 + 2*t], w1b = mbm[r1*32 + 2*t + 1];
            #pragma unroll
            for (int j = 0; j < 8; j++){
                uint32_t wr0 = (j<4)?w0a:w0b, wr1 = (j<4)?w1a:w1b;
                int bit = 8*(j&3) + 2*la;
                float e0 = ((wr0>>bit)&1u)     ? 0.f : __expf(s[j][0]);
                float e1 = ((wr0>>(bit+1))&1u) ? 0.f : __expf(s[j][1]);
                float e2 = ((wr1>>bit)&1u)     ? 0.f : __expf(s[j][2]);
                float e3 = ((wr1>>(bit+1))&1u) ? 0.f : __expf(s[j][3]);
                rs0 += e0 + e1;  rs1 += e2 + e3;
                s[j][0] = e0; s[j][1] = e1; s[j][2] = e2; s[j][3] = e3;
            }
        }
        // store unnormalized e to attn (rescaled in-place later)
        {
            float* a0p = outA + (brow + q0 + r0)*1024 + t*64 + 2*la;
            float* a1p = outA + (brow + q0 + r1)*1024 + t*64 + 2*la;
            #pragma unroll
            for (int j=0;j<8;j++){
                *(float2*)(a0p + 8*j) = make_float2(s[j][0], s[j][1]);
                *(float2*)(a1p + 8*j) = make_float2(s[j][2], s[j][3]);
            }
        }
        // PV with unnormalized e (O scaled once at the end)
        #pragma unroll
        for (int c2 = 0; c2 < 4; c2++){
            uint32_t ah[4], al[4];
            split2(s[2*c2][0],   s[2*c2][1],   ah[0], al[0]);
            split2(s[2*c2][2],   s[2*c2][3],   ah[1], al[1]);
            split2(s[2*c2+1][0], s[2*c2+1][1], ah[2], al[2]);
            split2(s[2*c2+1][2], s[2*c2+1][3], ah[3], al[3]);
            #pragma unroll
            for (int jp=0;jp<4;jp++){
                uint32_t bh[4], bl[4];
                int vrow = 16*c2 + ((ln>>3)&1)*8 + (ln&7);
                int vu = 2*jp + (ln>>4);
                ldsm4t(bh, swa(vh_base, vrow, vu));
                ldsm4t(bl, swa(vl_base, vrow, vu));
                mma_bf16(o[2*jp],   ah, bh);   mma_bf16(o[2*jp],   ah, bl);   mma_bf16(o[2*jp],   al, bh);
                mma_bf16(o[2*jp+1], ah, bh+2); mma_bf16(o[2*jp+1], ah, bl+2); mma_bf16(o[2*jp+1], al, bh+2);
            }
        }
        __syncthreads();   // readers done before next overwrite
    }

    // ---- rowsums -> scale factors ----
    rs0 += __shfl_xor_sync(~0u, rs0, 1); rs0 += __shfl_xor_sync(~0u, rs0, 2);
    rs1 += __shfl_xor_sync(~0u, rs1, 1); rs1 += __shfl_xor_sync(~0u, rs1, 2);
    const float qm0 = QMg[brow + q0 + r0], qm1 = QMg[brow + q0 + r1];
    const float scl0 = (rs0>0.f) ? (qm0/rs0) : 0.f, uad0 = (rs0>0.f) ? 0.f : qm0*(1.f/1024.f);
    const float scl1 = (rs1>0.f) ? (qm1/rs1) : 0.f, uad1 = (rs1>0.f) ? 0.f : qm1*(1.f/1024.f);

    // ---- O: scale in registers, store ----
    {
        float* oR = outR + (brow + q0)*64;
        #pragma unroll
        for (int j=0;j<8;j++){
            *(float2*)(oR + (size_t)r0*64 + 8*j + 2*la) = make_float2(o[j][0]*scl0, o[j][1]*scl0);
            *(float2*)(oR + (size_t)r1*64 + 8*j + 2*la) = make_float2(o[j][2]*scl1, o[j][3]*scl1);
        }
    }

    // ---- attn: rescale this warp's 16 rows in place ----
    __syncwarp();   // order e-stores before re-reads within the warp
    #pragma unroll 1
    for (int rr = 0; rr < 16; rr++){
        float scl_v = (rr < 8) ? __shfl_sync(~0u, scl0, rr*4) : __shfl_sync(~0u, scl1, (rr-8)*4);
        float uad_v = (rr < 8) ? __shfl_sync(~0u, uad0, rr*4) : __shfl_sync(~0u, uad1, (rr-8)*4);
        float4* ap = (float4*)(outA + (brow + q0 + 16*wid + rr)*1024);
        #pragma unroll
        for (int i = 0; i < 8; i++){
            float4 v = ap[ln + 32*i];
            v.x = v.x*scl_v + uad_v;  v.y = v.y*scl_v + uad_v;
            v.z = v.z*scl_v + uad_v;  v.w = v.w*scl_v + uad_v;
            ap[ln + 32*i] = v;
        }
    }
}

extern "C" void kernel_launch(void* const* d_in, const int* in_sizes, int n_in,
                              void* d_out, int out_size)
{
    const float* Kg  = (const float*)d_in[0];
    const float* Vg  = (const float*)d_in[1];
    const float* Qg  = (const float*)d_in[2];
    const int*   Mg  = (const int*)d_in[3];
    const float* QMg = (const float*)d_in[4];
    float* outR = (float*)d_out;
    float* outA = outR + (size_t)B_ * 1024 * 64;

    preconv<<<1024, 512>>>(Kg, Vg);
    cudaFuncSetAttribute(mha_hmma, cudaFuncAttributeMaxDynamicSharedMemorySize, SMEM_TOTAL);
    mha_hmma<<<B_ * 4, 512, SMEM_TOTAL>>>(Qg, Mg, QMg, outR, outA);
}

// round 17
// speedup vs baseline: 1.1263x; 1.0915x over previous
#include <cuda_runtime.h>
#include <cuda_bf16.h>
#include <cstdint>

#define B_ 32
// smem (bytes): K ring 2x16384 at 0 | V ring 2x16384 at 32768 | mask 16384
#define OFF_RING  0
#define OFF_VRING 32768
#define OFF_MASK  65536
#define SMEM_TOTAL 81920

// preconverted K/V scratch: bf16 hi/lo, row-major 128B rows
__device__ __align__(16) unsigned char g_kh[(size_t)B_*1024*128];
__device__ __align__(16) unsigned char g_kl[(size_t)B_*1024*128];
__device__ __align__(16) unsigned char g_vh[(size_t)B_*1024*128];
__device__ __align__(16) unsigned char g_vl[(size_t)B_*1024*128];
// packed mask bitmask: word (row*32 + w) = bits for k in [32w, 32w+32)
__device__ __align__(16) uint32_t g_mask[(size_t)B_*1024*32];

__device__ __forceinline__ uint32_t s2u(const void* p){
    uint32_t a; asm("{ .reg .u64 t; cvta.to.shared.u64 t, %1; cvt.u32.u64 %0, t; }":"=r"(a):"l"(p)); return a;
}
__device__ __forceinline__ void ldsm4(uint32_t* r, uint32_t a){
    asm volatile("ldmatrix.sync.aligned.m8n8.x4.shared.b16 {%0,%1,%2,%3}, [%4];"
        :"=r"(r[0]),"=r"(r[1]),"=r"(r[2]),"=r"(r[3]):"r"(a));
}
__device__ __forceinline__ void ldsm4t(uint32_t* r, uint32_t a){
    asm volatile("ldmatrix.sync.aligned.m8n8.x4.trans.shared.b16 {%0,%1,%2,%3}, [%4];"
        :"=r"(r[0]),"=r"(r[1]),"=r"(r[2]),"=r"(r[3]):"r"(a));
}
__device__ __forceinline__ void mma_bf16(float* c, const uint32_t* a, const uint32_t* b){
    asm volatile("mma.sync.aligned.m16n8k16.row.col.f32.bf16.bf16.f32 "
        "{%0,%1,%2,%3}, {%4,%5,%6,%7}, {%8,%9}, {%0,%1,%2,%3};"
        :"+f"(c[0]),"+f"(c[1]),"+f"(c[2]),"+f"(c[3])
        :"r"(a[0]),"r"(a[1]),"r"(a[2]),"r"(a[3]),"r"(b[0]),"r"(b[1]));
}
__device__ __forceinline__ uint32_t swa(uint32_t base, int row, int u){
    return base + (uint32_t)row*128u + (uint32_t)((u ^ (row & 7)) << 4);
}
__device__ __forceinline__ void split2(float x, float y, uint32_t &hi, uint32_t &lo){
    __nv_bfloat16 hx=__float2bfloat16(x), hy=__float2bfloat16(y);
    __nv_bfloat16 lx=__float2bfloat16(x-__bfloat162float(hx)), ly=__float2bfloat16(y-__bfloat162float(hy));
    hi = ((uint32_t)__bfloat16_as_ushort(hy)<<16)|__bfloat16_as_ushort(hx);
    lo = ((uint32_t)__bfloat16_as_ushort(ly)<<16)|__bfloat16_as_ushort(lx);
}
__device__ __forceinline__ void cvt_store(float4 v, char* smc, int offH, int offL, int row, int c4){
    uint32_t o = (uint32_t)row*128u + (uint32_t)(((((c4>>1) ^ (row&7)) << 4)) | ((c4&1)<<3));
    uint32_t h0, l0, h1, l1;
    split2(v.x, v.y, h0, l0);
    split2(v.z, v.w, h1, l1);
    *(uint2*)(smc + offH + o) = make_uint2(h0, h1);
    *(uint2*)(smc + offL + o) = make_uint2(l0, l1);
}
__device__ __forceinline__ void cpa16(uint32_t dst, const void* src){
    asm volatile("cp.async.cg.shared.global [%0], [%1], 16;" :: "r"(dst), "l"(src));
}
#define CPA_COMMIT() asm volatile("cp.async.commit_group;" ::: "memory")
#define CPA_WAIT1()  asm volatile("cp.async.wait_group 1;" ::: "memory")
#define CPA_WAIT0()  asm volatile("cp.async.wait_group 0;" ::: "memory")

// load one 64-row tile (hi 8KB + lo 8KB) into a 16KB slot; 1024 16B chunks, 4/thread
__device__ __forceinline__ void load_tile(uint32_t slotbase, const unsigned char* ghi,
                                          const unsigned char* glo, size_t row0, int tid){
    #pragma unroll
    for (int p = 0; p < 4; p++){
        int id = tid + p*256;
        int hl = id >> 9, rem = id & 511, r = rem >> 3, u = rem & 7;
        uint32_t dst = slotbase + (uint32_t)hl*8192u + (uint32_t)r*128u + (uint32_t)((u ^ (r & 7)) << 4);
        const unsigned char* src = (hl ? glo : ghi) + (row0 + r)*128 + u*16;
        cpa16(dst, src);
    }
}

__global__ void __launch_bounds__(512) preconv(const float* __restrict__ K, const float* __restrict__ V){
    size_t idx = (size_t)blockIdx.x * 512 + threadIdx.x;
    size_t row = idx >> 4, c4 = idx & 15;
    float4 kv = ((const float4*)K)[idx];
    float4 vv = ((const float4*)V)[idx];
    uint32_t h0,l0,h1,l1;
    split2(kv.x, kv.y, h0, l0); split2(kv.z, kv.w, h1, l1);
    *(uint2*)(g_kh + row*128 + c4*8) = make_uint2(h0, h1);
    *(uint2*)(g_kl + row*128 + c4*8) = make_uint2(l0, l1);
    split2(vv.x, vv.y, h0, l0); split2(vv.z, vv.w, h1, l1);
    *(uint2*)(g_vh + row*128 + c4*8) = make_uint2(h0, h1);
    *(uint2*)(g_vl + row*128 + c4*8) = make_uint2(l0, l1);
}

// pack int32 mask (nonzero = masked) into 1-bit-per-element bitmask words
__global__ void __launch_bounds__(256) packmask(const int* __restrict__ M){
    size_t idx = (size_t)blockIdx.x * 256 + threadIdx.x;   // one output word each
    const int4* mp = (const int4*)(M + idx*32);
    uint32_t bits = 0;
    #pragma unroll
    for (int m2 = 0; m2 < 8; m2++){
        int4 v = mp[m2];
        bits |= ((v.x?1u:0u)|(v.y?2u:0u)|(v.z?4u:0u)|(v.w?8u:0u)) << (4*m2);
    }
    g_mask[idx] = bits;
}

__global__ void __launch_bounds__(256, 2)
mha_hmma(const float* __restrict__ Qg,
         const float* __restrict__ QMg, float* __restrict__ outR, float* __restrict__ outA)
{
    extern __shared__ char smc[];
    const uint32_t sb = s2u(smc);
    const int tid = threadIdx.x, wid = tid>>5, ln = tid&31;
    const int la = ln&3;
    const int r0 = 16*wid + (ln>>2), r1 = r0 + 8;
    const int b = blockIdx.x>>3, q0 = (blockIdx.x&7)*128;
    const size_t brow = (size_t)b*1024;

    // ---- prologue: Q (x0.125) -> bf16 split into ring area; copy packed mask ----
    const float4* gQ4 = (const float4*)(Qg + (brow + q0)*64);
    for (int i = tid; i < 2048; i += 256){
        float4 v = gQ4[i];
        v.x*=0.125f; v.y*=0.125f; v.z*=0.125f; v.w*=0.125f;
        cvt_store(v, smc, OFF_RING, OFF_RING + 16384, i>>4, i&15);
    }
    uint32_t* mbm = (uint32_t*)(smc + OFF_MASK);
    const uint4* gBM = (const uint4*)(g_mask + (brow + q0)*32);
    #pragma unroll
    for (int p = 0; p < 4; p++)
        ((uint4*)mbm)[tid + p*256] = gBM[tid + p*256];
    __syncthreads();
    // Q fragments register-resident
    const int qrow = 16*wid + (ln&15);
    uint32_t Qh[4][4], Ql[4][4];
    #pragma unroll
    for (int c = 0; c < 4; c++){
        ldsm4(Qh[c], swa(sb + OFF_RING,         qrow, 2*c + (ln>>4)));
        ldsm4(Ql[c], swa(sb + OFF_RING + 16384, qrow, 2*c + (ln>>4)));
    }
    __syncthreads();   // ring free for K

    // ================= single pass: QK -> e (unnormalized) -> attn store + PV =================
    float rs0 = 0.f, rs1 = 0.f;
    float o[8][4];
    #pragma unroll
    for (int j=0;j<8;j++){ o[j][0]=0.f; o[j][1]=0.f; o[j][2]=0.f; o[j][3]=0.f; }

    load_tile(sb + OFF_RING,  g_kh, g_kl, brow, tid);
    load_tile(sb + OFF_VRING, g_vh, g_vl, brow, tid); CPA_COMMIT();
    for (int t = 0; t < 16; t++){
        if (t < 15){
            load_tile(sb + OFF_RING  + ((t+1)&1)*16384, g_kh, g_kl, brow + 64*(t+1), tid);
            load_tile(sb + OFF_VRING + ((t+1)&1)*16384, g_vh, g_vl, brow + 64*(t+1), tid);
            CPA_COMMIT();
        }
        if (t < 15) CPA_WAIT1(); else CPA_WAIT0();
        __syncthreads();
        const uint32_t bh_base = sb + OFF_RING  + (t&1)*16384, bl_base = bh_base + 8192;
        const uint32_t vh_base = sb + OFF_VRING + (t&1)*16384, vl_base = vh_base + 8192;
        float s[8][4];
        #pragma unroll
        for (int j=0;j<8;j++){ s[j][0]=0.f; s[j][1]=0.f; s[j][2]=0.f; s[j][3]=0.f; }
        #pragma unroll
        for (int c = 0; c < 4; c++){
            #pragma unroll
            for (int jp = 0; jp < 4; jp++){
                uint32_t bh[4], bl[4];
                int krow = 16*jp + ((ln>>4)<<3) + (ln&7);
                int ku = 2*c + ((ln>>3)&1);
                ldsm4(bh, swa(bh_base, krow, ku));
                ldsm4(bl, swa(bl_base, krow, ku));
                mma_bf16(s[2*jp],   Qh[c], bh);   mma_bf16(s[2*jp],   Qh[c], bl);   mma_bf16(s[2*jp],   Ql[c], bh);
                mma_bf16(s[2*jp+1], Qh[c], bh+2); mma_bf16(s[2*jp+1], Qh[c], bl+2); mma_bf16(s[2*jp+1], Ql[c], bh+2);
            }
        }
        // masked exp (unnormalized) + rowsum accumulation
        {
            uint32_t w0a = mbm[r0*32 + 2*t], w0b = mbm[r0*32 + 2*t + 1];
            uint32_t w1a = mbm[r1*32 + 2*t], w1b = mbm[r1*32 + 2*t + 1];
            #pragma unroll
            for (int j = 0; j < 8; j++){
                uint32_t wr0 = (j<4)?w0a:w0b, wr1 = (j<4)?w1a:w1b;
                int bit = 8*(j&3) + 2*la;
                float e0 = ((wr0>>bit)&1u)     ? 0.f : __expf(s[j][0]);
                float e1 = ((wr0>>(bit+1))&1u) ? 0.f : __expf(s[j][1]);
                float e2 = ((wr1>>bit)&1u)     ? 0.f : __expf(s[j][2]);
                float e3 = ((wr1>>(bit+1))&1u) ? 0.f : __expf(s[j][3]);
                rs0 += e0 + e1;  rs1 += e2 + e3;
                s[j][0] = e0; s[j][1] = e1; s[j][2] = e2; s[j][3] = e3;
            }
        }
        // store unnormalized e to attn (rescaled in-place later)
        {
            float* a0p = outA + (brow + q0 + r0)*1024 + t*64 + 2*la;
            float* a1p = outA + (brow + q0 + r1)*1024 + t*64 + 2*la;
            #pragma unroll
            for (int j=0;j<8;j++){
                *(float2*)(a0p + 8*j) = make_float2(s[j][0], s[j][1]);
                *(float2*)(a1p + 8*j) = make_float2(s[j][2], s[j][3]);
            }
        }
        // PV with unnormalized e (O scaled once at the end)
        #pragma unroll
        for (int c2 = 0; c2 < 4; c2++){
            uint32_t ah[4], al[4];
            split2(s[2*c2][0],   s[2*c2][1],   ah[0], al[0]);
            split2(s[2*c2][2],   s[2*c2][3],   ah[1], al[1]);
            split2(s[2*c2+1][0], s[2*c2+1][1], ah[2], al[2]);
            split2(s[2*c2+1][2], s[2*c2+1][3], ah[3], al[3]);
            #pragma unroll
            for (int jp=0;jp<4;jp++){
                uint32_t bh[4], bl[4];
                int vrow = 16*c2 + ((ln>>3)&1)*8 + (ln&7);
                int vu = 2*jp + (ln>>4);
                ldsm4t(bh, swa(vh_base, vrow, vu));
                ldsm4t(bl, swa(vl_base, vrow, vu));
                mma_bf16(o[2*jp],   ah, bh);   mma_bf16(o[2*jp],   ah, bl);   mma_bf16(o[2*jp],   al, bh);
                mma_bf16(o[2*jp+1], ah, bh+2); mma_bf16(o[2*jp+1], ah, bl+2); mma_bf16(o[2*jp+1], al, bh+2);
            }
        }
        __syncthreads();   // readers done before next overwrite
    }

    // ---- rowsums -> scale factors ----
    rs0 += __shfl_xor_sync(~0u, rs0, 1); rs0 += __shfl_xor_sync(~0u, rs0, 2);
    rs1 += __shfl_xor_sync(~0u, rs1, 1); rs1 += __shfl_xor_sync(~0u, rs1, 2);
    const float qm0 = QMg[brow + q0 + r0], qm1 = QMg[brow + q0 + r1];
    const float scl0 = (rs0>0.f) ? (qm0/rs0) : 0.f, uad0 = (rs0>0.f) ? 0.f : qm0*(1.f/1024.f);
    const float scl1 = (rs1>0.f) ? (qm1/rs1) : 0.f, uad1 = (rs1>0.f) ? 0.f : qm1*(1.f/1024.f);

    // ---- O: scale in registers, store ----
    {
        float* oR = outR + (brow + q0)*64;
        #pragma unroll
        for (int j=0;j<8;j++){
            *(float2*)(oR + (size_t)r0*64 + 8*j + 2*la) = make_float2(o[j][0]*scl0, o[j][1]*scl0);
            *(float2*)(oR + (size_t)r1*64 + 8*j + 2*la) = make_float2(o[j][2]*scl1, o[j][3]*scl1);
        }
    }

    // ---- attn: rescale this warp's 16 rows in place ----
    __syncwarp();   // order e-stores before re-reads within the warp
    #pragma unroll 1
    for (int rr = 0; rr < 16; rr++){
        float scl_v = (rr < 8) ? __shfl_sync(~0u, scl0, rr*4) : __shfl_sync(~0u, scl1, (rr-8)*4);
        float uad_v = (rr < 8) ? __shfl_sync(~0u, uad0, rr*4) : __shfl_sync(~0u, uad1, (rr-8)*4);
        float4* ap = (float4*)(outA + (brow + q0 + 16*wid + rr)*1024);
        #pragma unroll
        for (int i = 0; i < 8; i++){
            float4 v = ap[ln + 32*i];
            v.x = v.x*scl_v + uad_v;  v.y = v.y*scl_v + uad_v;
            v.z = v.z*scl_v + uad_v;  v.w = v.w*scl_v + uad_v;
            ap[ln + 32*i] = v;
        }
    }
}

extern "C" void kernel_launch(void* const* d_in, const int* in_sizes, int n_in,
                              void* d_out, int out_size)
{
    const float* Kg  = (const float*)d_in[0];
    const float* Vg  = (const float*)d_in[1];
    const float* Qg  = (const float*)d_in[2];
    const int*   Mg  = (const int*)d_in[3];
    const float* QMg = (const float*)d_in[4];
    float* outR = (float*)d_out;
    float* outA = outR + (size_t)B_ * 1024 * 64;

    preconv<<<1024, 512>>>(Kg, Vg);
    packmask<<<4096, 256>>>(Mg);
    cudaFuncSetAttribute(mha_hmma, cudaFuncAttributeMaxDynamicSharedMemorySize, SMEM_TOTAL);
    mha_hmma<<<B_ * 8, 256, SMEM_TOTAL>>>(Qg, QMg, outR, outA);
}